// round 5
// baseline (speedup 1.0000x reference)
#include <cuda_runtime.h>
#include <cuda_bf16.h>

// Sinkhorn EMD, N=M=1024, D=3, iters=3000 (read from input), eps=0.01.
// Single persistent kernel: 148 CTAs x 256 threads, all co-resident on the
// 152-SM GB300, synchronized with a software grid barrier (6000 barriers).
// C and C^T are built once per launch into __device__ scratch; per-SM slices
// stay hot in L1 for the whole launch.

#define Nn    1024
#define NCTA  148
#define NTH   256

#define S_CONST   144.2695040888963f          // log2(e) / eps  (eps = 0.01)
#define EPS_LOGA  (-0.069314718055994531f)    // eps * (-ln 1024)
#define EPS_LN2   (0.0069314718055994531f)    // eps * ln 2

__device__ float d_C [Nn * Nn];
__device__ float d_CT[Nn * Nn];
__device__ float d_f [Nn];
__device__ float d_g [Nn];
__device__ float d_rowsum[Nn];
__device__ unsigned d_cnt = 0;
__device__ unsigned d_gen = 0;

__device__ __forceinline__ float ex2f(float x) {
    float r;
    asm("ex2.approx.ftz.f32 %0, %1;" : "=f"(r) : "f"(x));
    return r;
}

// Sense-reversing grid barrier. Safe across launches: d_cnt returns to 0 at
// every release, d_gen is monotonically increasing (wrap-safe equality spin).
__device__ __forceinline__ void grid_sync() {
    __syncthreads();
    if (threadIdx.x == 0) {
        volatile unsigned* vg = (volatile unsigned*)&d_gen;
        unsigned g0 = *vg;                      // read generation BEFORE arriving
        __threadfence();                        // make this CTA's writes visible
        unsigned prev = atomicAdd(&d_cnt, 1u);
        if (prev == NCTA - 1) {
            *(volatile unsigned*)&d_cnt = 0u;   // reset before release
            __threadfence();
            *vg = g0 + 1u;                      // release
        } else {
            while (*vg == g0) { }               // spin on L2
        }
        __threadfence();                        // acquire
    }
    __syncthreads();
}

// One Sinkhorn half-update: dout[row] = eps*log_a - eps*LSE_j((din[j]-Cm[row,j])/eps)
// Warp w of CTA c owns row = c + 148*w (w in [0,7), rows balanced 6-7 per CTA).
// Args are computed in the exp2 domain (pre-multiplied by S_CONST) and cached
// in 32 registers per lane between the max pass and the sum pass.
__device__ __forceinline__ void half_pass(const float* __restrict__ Cm,
                                          const float* __restrict__ din,
                                          float* __restrict__ dout,
                                          float* sh) {
    // stage sh[j] = S * din[j]
    for (int j = threadIdx.x; j < Nn; j += NTH) sh[j] = S_CONST * din[j];
    __syncthreads();

    const int w    = threadIdx.x >> 5;
    const int lane = threadIdx.x & 31;
    const int row  = (int)blockIdx.x + NCTA * w;
    if (w < 7 && row < Nn) {
        const float4* c4 = (const float4*)(Cm + (size_t)row * Nn);
        const float4* s4 = (const float4*)sh;
        float args[32];
        float m = -3.4e38f;
#pragma unroll
        for (int k = 0; k < 8; k++) {
            const int idx = (k << 5) + lane;
            const float4 c  = c4[idx];
            const float4 gv = s4[idx];
            const float a0 = fmaf(c.x, -S_CONST, gv.x);
            const float a1 = fmaf(c.y, -S_CONST, gv.y);
            const float a2 = fmaf(c.z, -S_CONST, gv.z);
            const float a3 = fmaf(c.w, -S_CONST, gv.w);
            args[4 * k + 0] = a0; args[4 * k + 1] = a1;
            args[4 * k + 2] = a2; args[4 * k + 3] = a3;
            m = fmaxf(m, fmaxf(fmaxf(a0, a1), fmaxf(a2, a3)));
        }
#pragma unroll
        for (int off = 16; off; off >>= 1)
            m = fmaxf(m, __shfl_xor_sync(0xffffffffu, m, off));
        float sum = 0.f;
#pragma unroll
        for (int k = 0; k < 32; k++) sum += ex2f(args[k] - m);
#pragma unroll
        for (int off = 16; off; off >>= 1)
            sum += __shfl_xor_sync(0xffffffffu, sum, off);
        if (lane == 0)
            dout[row] = EPS_LOGA - EPS_LN2 * (m + log2f(sum));
    }
    // no trailing sync needed: the following grid_sync() starts with __syncthreads()
}

__global__ void __launch_bounds__(NTH)
emd_kernel(const float* __restrict__ tgt,     // [1024,3]
           const float* __restrict__ outp,    // [1024,3]
           const int*   __restrict__ iters_ptr,
           float*       __restrict__ out) {
    __shared__ __align__(16) float sh[Nn];
    __shared__ float red[NTH];
    const int tid  = threadIdx.x;
    const int gtid = (int)blockIdx.x * NTH + tid;
    const int nthr = NCTA * NTH;

    // ---- Phase A: build C and C^T, zero f and g (re-done every launch) ----
    for (int p = gtid; p < Nn * Nn; p += nthr) {
        const int i = p >> 10;
        const int j = p & (Nn - 1);
        const float dx = tgt[i * 3 + 0] - outp[j * 3 + 0];
        const float dy = tgt[i * 3 + 1] - outp[j * 3 + 1];
        const float dz = tgt[i * 3 + 2] - outp[j * 3 + 2];
        const float c = dx * dx + dy * dy + dz * dz;
        d_C[p] = c;
        d_CT[(j << 10) | i] = c;
    }
    if (gtid < Nn) { d_f[gtid] = 0.f; d_g[gtid] = 0.f; }
    grid_sync();

    // ---- Phase B: Sinkhorn iterations ----
    const int iters = iters_ptr ? iters_ptr[0] : 3000;
    for (int it = 0; it < iters; it++) {
        half_pass(d_C,  d_g, d_f, sh);   // f-update (rows)
        grid_sync();
        half_pass(d_CT, d_f, d_g, sh);   // g-update (cols, via C^T)
        grid_sync();
    }

    // ---- Phase C: objective  sum_ij exp((f_i + g_j - C_ij)/eps) * C_ij ----
    for (int j = tid; j < Nn; j += NTH) sh[j] = S_CONST * d_g[j];
    __syncthreads();
    {
        const int w    = tid >> 5;
        const int lane = tid & 31;
        const int row  = (int)blockIdx.x + NCTA * w;
        if (w < 7 && row < Nn) {
            const float  sf = S_CONST * d_f[row];
            const float4* c4 = (const float4*)(d_C + (size_t)row * Nn);
            const float4* s4 = (const float4*)sh;
            float acc = 0.f;
#pragma unroll
            for (int k = 0; k < 8; k++) {
                const int idx = (k << 5) + lane;
                const float4 c  = c4[idx];
                const float4 gv = s4[idx];
                acc += ex2f(fmaf(c.x, -S_CONST, sf + gv.x)) * c.x;
                acc += ex2f(fmaf(c.y, -S_CONST, sf + gv.y)) * c.y;
                acc += ex2f(fmaf(c.z, -S_CONST, sf + gv.z)) * c.z;
                acc += ex2f(fmaf(c.w, -S_CONST, sf + gv.w)) * c.w;
            }
#pragma unroll
            for (int off = 16; off; off >>= 1)
                acc += __shfl_xor_sync(0xffffffffu, acc, off);
            if (lane == 0) d_rowsum[row] = acc;
        }
    }
    grid_sync();

    // ---- Deterministic final reduction by CTA 0 ----
    if (blockIdx.x == 0) {
        float v = 0.f;
        for (int k = tid; k < Nn; k += NTH) v += d_rowsum[k];
        red[tid] = v;
        __syncthreads();
        for (int s = NTH >> 1; s > 0; s >>= 1) {
            if (tid < s) red[tid] += red[tid + s];
            __syncthreads();
        }
        if (tid == 0) out[0] = red[0];
    }
}

extern "C" void kernel_launch(void* const* d_in, const int* in_sizes, int n_in,
                              void* d_out, int out_size) {
    const float* tgt  = (const float*)d_in[0];
    const float* outp = (const float*)d_in[1];
    const int*   itp  = (n_in >= 3) ? (const int*)d_in[2] : nullptr;
    (void)in_sizes; (void)out_size;
    emd_kernel<<<NCTA, NTH>>>(tgt, outp, itp, (float*)d_out);
}

// round 9
// speedup vs baseline: 1.4346x; 1.4346x over previous
#include <cuda_runtime.h>
#include <cuda_bf16.h>

// Sinkhorn EMD, N=M=1024, D=3, eps=0.01, iters read from input (3000).
// Persistent kernel, 128 CTAs x 256 threads (8 warps; warp w of CTA b owns
// global row/col index b*8+w).
//
// SYNC: verbatim copy of the Round-5 barrier that PASSED (rel_err 4e-7):
// sense-reversing counter + generation word, with all three __threadfence
// placements intact. The fences emit CCTL.IVALL (L1 flush) -- which is now
// harmless, because the hot data (the cost-matrix slices) lives in SHARED
// MEMORY, not L1:
//   * each CTA builds its 8 rows of S*C and 8 rows of S*C^T (64 KB dynamic
//     SMEM) directly from the 24 KB point clouds in Phase A (local work,
//     no grid sync needed);
//   * the inner loop is conflict-free LDS.128 + MUFU ex2, with only a 4 KB
//     staging read of f/g from L2 per half-pass (made coherent by the
//     barrier's fences, exactly as in Round 5).
//
// Math in the exp2 domain scaled by S = log2(e)/eps:
//   S*eps*ln2 == 1 and S*eps*ln(1024) == 10, so
//   S*f_row = -10 - m - log2( sum_j exp2( S*g_j - S*C_rj - m ) ).

#define Nn      1024
#define NCTA    128
#define NTH     256
#define S_CONST 144.26950408889634074f   // log2(e)/eps, eps = 0.01
#define INV_S   0.0069314718055994531f   // eps*ln2 = 1/S

#define SMEM_BYTES ((8 * 1024 * 2 + 1024) * 4)   // sSC + sSCT + staging = 68 KB

__device__ __align__(16) float d_Sf[Nn];      // S * f
__device__ __align__(16) float d_Sg[Nn];      // S * g
__device__ __align__(16) float d_rowsum[Nn];
__device__ unsigned d_cnt = 0;                // returns to 0 at every release
__device__ unsigned d_gen = 0;                // monotone generation (wrap-safe)

__device__ __forceinline__ float ex2f(float x) {
    float r;
    asm("ex2.approx.ftz.f32 %0, %1;" : "=f"(r) : "f"(x));
    return r;
}

// ---- Round-5 grid barrier, VERBATIM (proven correct on this problem). ----
__device__ __forceinline__ void grid_sync() {
    __syncthreads();
    if (threadIdx.x == 0) {
        volatile unsigned* vg = (volatile unsigned*)&d_gen;
        unsigned g0 = *vg;                      // read generation BEFORE arriving
        __threadfence();                        // make this CTA's writes visible
        unsigned prev = atomicAdd(&d_cnt, 1u);
        if (prev == NCTA - 1) {
            *(volatile unsigned*)&d_cnt = 0u;   // reset before release
            __threadfence();
            *vg = g0 + 1u;                      // release
        } else {
            while (*vg == g0) { }               // spin on L2
        }
        __threadfence();                        // acquire (+ IVALL -> L1 fresh)
    }
    __syncthreads();
}

// One Sinkhorn half-update. sC = this CTA's SMEM slice [8][1024].
//   dout[row] = -10 - m - log2( sum_j exp2( din[j] - sC[w][j] - m ) )
__device__ __forceinline__ void half_pass(const float* __restrict__ sC,
                                          const float* __restrict__ din, // global (null => zeros)
                                          float* __restrict__ dout,      // global, plain store
                                          float4* __restrict__ shg,
                                          int w, int lane, int row) {
    // Stage din into shared: one 16B load per thread (plain load, like R5 --
    // fresh because the barrier's acquire fence invalidated L1).
    if (din)
        shg[threadIdx.x] = ((const float4*)din)[threadIdx.x];
    else
        shg[threadIdx.x] = make_float4(0.f, 0.f, 0.f, 0.f);
    __syncthreads();

    const float4* c4 = (const float4*)(sC + (w << 10));
    float args[32];
    float m = -3.4e38f;
#pragma unroll
    for (int k = 0; k < 8; k++) {
        const int idx = (k << 5) + lane;
        const float4 c = c4[idx];    // LDS.128, conflict-free
        const float4 g = shg[idx];   // LDS.128, conflict-free
        const float a0 = g.x - c.x;
        const float a1 = g.y - c.y;
        const float a2 = g.z - c.z;
        const float a3 = g.w - c.w;
        args[4 * k + 0] = a0; args[4 * k + 1] = a1;
        args[4 * k + 2] = a2; args[4 * k + 3] = a3;
        m = fmaxf(m, fmaxf(fmaxf(a0, a1), fmaxf(a2, a3)));
    }
#pragma unroll
    for (int off = 16; off; off >>= 1)
        m = fmaxf(m, __shfl_xor_sync(0xffffffffu, m, off));
    float sum = 0.f;
#pragma unroll
    for (int k = 0; k < 32; k++) sum += ex2f(args[k] - m);
#pragma unroll
    for (int off = 16; off; off >>= 1)
        sum += __shfl_xor_sync(0xffffffffu, sum, off);
    if (lane == 0)
        dout[row] = -10.0f - m - __log2f(sum);   // plain store (fenced in grid_sync)
}

__global__ void __launch_bounds__(NTH, 1)
emd_kernel(const float* __restrict__ tgt,    // [1024,3]
           const float* __restrict__ outp,   // [1024,3]
           const int*   __restrict__ iters_ptr,
           float*       __restrict__ out) {
    extern __shared__ __align__(16) float smem[];
    float*  sSC  = smem;                        // [8][1024]  S*C rows
    float*  sSCT = smem + 8 * 1024;             // [8][1024]  S*C^T rows
    float4* shg  = (float4*)(smem + 16 * 1024); // 1024-float staging
    __shared__ float red[NTH];

    const int tid  = threadIdx.x;
    const int w    = tid >> 5;
    const int lane = tid & 31;
    const int bid  = (int)blockIdx.x;
    const int row  = (bid << 3) + w;            // this warp's global row/col

    // ---- Phase A (CTA-local): build SMEM cost slices from point clouds ----
    {
        const float tx = tgt[row * 3 + 0], ty = tgt[row * 3 + 1], tz = tgt[row * 3 + 2];
        for (int j = lane; j < Nn; j += 32) {
            const float dx = tx - outp[j * 3 + 0];
            const float dy = ty - outp[j * 3 + 1];
            const float dz = tz - outp[j * 3 + 2];
            sSC[(w << 10) + j] = S_CONST * (dx * dx + dy * dy + dz * dz);
        }
        const float ox = outp[row * 3 + 0], oy = outp[row * 3 + 1], oz = outp[row * 3 + 2];
        for (int i = lane; i < Nn; i += 32) {
            const float dx = tgt[i * 3 + 0] - ox;
            const float dy = tgt[i * 3 + 1] - oy;
            const float dz = tgt[i * 3 + 2] - oz;
            sSCT[(w << 10) + i] = S_CONST * (dx * dx + dy * dy + dz * dz);
        }
    }
    __syncthreads();

    // ---- Phase B: Sinkhorn iterations ----
    const int iters = iters_ptr ? iters_ptr[0] : 3000;
    for (int it = 0; it < iters; it++) {
        half_pass(sSC, (it == 0) ? (const float*)0 : d_Sg, d_Sf, shg, w, lane, row);
        grid_sync();
        half_pass(sSCT, d_Sf, d_Sg, shg, w, lane, row);
        grid_sync();
    }

    // ---- Phase C: rowsum_i = sum_j exp2(Sf_i + Sg_j - SC_ij) * SC_ij ----
    shg[tid] = ((const float4*)d_Sg)[tid];
    __syncthreads();
    {
        const float sfr = d_Sf[row];
        const float4* c4 = (const float4*)(sSC + (w << 10));
        float acc = 0.f;
#pragma unroll
        for (int k = 0; k < 8; k++) {
            const int idx = (k << 5) + lane;
            const float4 c = c4[idx];
            const float4 g = shg[idx];
            acc += ex2f(sfr + g.x - c.x) * c.x;
            acc += ex2f(sfr + g.y - c.y) * c.y;
            acc += ex2f(sfr + g.z - c.z) * c.z;
            acc += ex2f(sfr + g.w - c.w) * c.w;
        }
#pragma unroll
        for (int off = 16; off; off >>= 1)
            acc += __shfl_xor_sync(0xffffffffu, acc, off);
        if (lane == 0) d_rowsum[row] = acc;
    }
    grid_sync();

    // ---- Deterministic final reduction by CTA 0; scale by 1/S ----
    if (bid == 0) {
        float v = 0.f;
        for (int k = tid; k < Nn; k += NTH) v += d_rowsum[k];
        red[tid] = v;
        __syncthreads();
        for (int s = NTH >> 1; s > 0; s >>= 1) {
            if (tid < s) red[tid] += red[tid + s];
            __syncthreads();
        }
        if (tid == 0) out[0] = red[0] * INV_S;
    }
    // d_cnt is back to 0 after every release and d_gen is monotone/wrap-safe,
    // so graph replays need no extra reset handshake (same as Round 5).
}

extern "C" void kernel_launch(void* const* d_in, const int* in_sizes, int n_in,
                              void* d_out, int out_size) {
    const float* tgt  = (const float*)d_in[0];
    const float* outp = (const float*)d_in[1];
    const int*   itp  = (n_in >= 3) ? (const int*)d_in[2] : nullptr;
    (void)in_sizes; (void)out_size;
    cudaFuncSetAttribute(emd_kernel, cudaFuncAttributeMaxDynamicSharedMemorySize,
                         SMEM_BYTES);
    emd_kernel<<<NCTA, NTH, SMEM_BYTES>>>(tgt, outp, itp, (float*)d_out);
}

// round 10
// speedup vs baseline: 1.4914x; 1.0396x over previous
#include <cuda_runtime.h>
#include <cuda_bf16.h>

// Sinkhorn EMD, N=M=1024, D=3, eps=0.01, iters read from input (3000).
// Persistent kernel, 128 CTAs x 256 threads; warp w of CTA b owns row b*8+w.
//
// R9 (passed, 16.85ms) showed sync latency dominates (~4500 cyc/barrier).
// Root cause per B300 atomics model: 128 atomicAdds to ONE address serialize
// at ~32 cyc/op (~4000 cyc). This round trees the arrivals:
//   16 group counters (8 CTAs each, 256B apart -> distinct L2 slices) + root.
// Double-buffered (by barrier parity) counters need NO reset fence: the
// leader's plain reset store is drained by its own trailing acquire
// __threadfence, and the counter is next used only at barrier n+2, which
// happens-after that fence (n+1 completion requires this leader's arrival).
// Fence placement is otherwise identical to the PROVEN R9 barrier:
//   __syncthreads -> [tid0] writer __threadfence -> arrivals -> spin on
//   volatile d_gen -> acquire __threadfence (IVALL) -> __syncthreads.
// d_gen is monotone; per-launch base read in Phase A (safe: gen cannot
// advance before all CTAs arrive at barrier 1) => graph-replay safe.
//
// Cost matrix in SMEM (64KB/CTA, built locally in Phase A) => IVALL is
// harmless. f/g read directly as 8 plain LDG.128 per warp (fresh post-IVALL),
// published with plain stores covered by the writer fence.
//
// Math in the exp2 domain scaled by S = log2(e)/eps (S*eps*ln2 == 1,
// S*eps*ln(1024) == 10):  S*f_row = -10 - m - log2(sum_j exp2(args_j - m)).

#define Nn      1024
#define NCTA    128
#define NTH     256
#define S_CONST 144.26950408889634074f   // log2(e)/eps, eps = 0.01
#define INV_S   0.0069314718055994531f   // eps*ln2 = 1/S

#define SMEM_BYTES (8 * 1024 * 2 * 4)    // sSC + sSCT = 64 KB

__device__ __align__(16) float d_Sf[Nn];      // S * f
__device__ __align__(16) float d_Sg[Nn];      // S * g
__device__ __align__(16) float d_rowsum[Nn];
__device__ unsigned d_gen = 0;                 // monotone release word
__device__ unsigned d_grp[2][16 * 64];         // parity-buffered group counters (256B stride)
__device__ unsigned d_root[2 * 64];            // parity-buffered root counters

__device__ __forceinline__ float ex2f(float x) {
    float r;
    asm("ex2.approx.ftz.f32 %0, %1;" : "=f"(r) : "f"(x));
    return r;
}

// Tree grid barrier. n_abs = absolute (base-adjusted) barrier index, gi =
// group index (blockIdx.x >> 3). Proven R9 fence placement; tree arrivals.
__device__ __forceinline__ void tree_sync(unsigned n_abs, int gi) {
    __syncthreads();
    if (threadIdx.x == 0) {
        __threadfence();                              // writer release (as R9)
        const int pp = (int)(n_abs & 1u);
        unsigned gprev = atomicAdd(&d_grp[pp][gi << 6], 1u);
        if (gprev == 7u) {                            // group leader
            unsigned rprev = atomicAdd(&d_root[pp << 6], 1u);
            d_grp[pp][gi << 6] = 0u;                  // drained by trailing fence;
                                                      // next use at barrier n+2
            if (rprev == 15u) {                       // root leader: release
                d_root[pp << 6] = 0u;
                *(volatile unsigned*)&d_gen = n_abs + 1u;
            }
        }
        while (*(volatile unsigned*)&d_gen < n_abs + 1u) { }
        __threadfence();                              // acquire + IVALL (as R9)
    }
    __syncthreads();
}

// One Sinkhorn half-update, fully warp-independent (no intra-CTA syncs).
//   dout[row] = -10 - m - log2( sum_j exp2( din[j] - sC[w][j] - m ) )
template <bool HASG>
__device__ __forceinline__ void half_pass(const float* __restrict__ sC,
                                          const float* __restrict__ din, // global
                                          float* __restrict__ dout,      // global
                                          int w, int lane, int row) {
    const float4* c4 = (const float4*)(sC + (w << 10));
    const float4* g4 = (const float4*)din;
    float args[32];
    float m = -3.4e38f;
#pragma unroll
    for (int k = 0; k < 8; k++) {
        const int idx = (k << 5) + lane;
        const float4 c = c4[idx];                       // LDS.128, conflict-free
        const float4 g = HASG ? g4[idx]                 // plain LDG.128 (fresh post-IVALL)
                              : make_float4(0.f, 0.f, 0.f, 0.f);
        const float a0 = g.x - c.x;
        const float a1 = g.y - c.y;
        const float a2 = g.z - c.z;
        const float a3 = g.w - c.w;
        args[4 * k + 0] = a0; args[4 * k + 1] = a1;
        args[4 * k + 2] = a2; args[4 * k + 3] = a3;
        m = fmaxf(m, fmaxf(fmaxf(a0, a1), fmaxf(a2, a3)));
    }
#pragma unroll
    for (int off = 16; off; off >>= 1)
        m = fmaxf(m, __shfl_xor_sync(0xffffffffu, m, off));
    float sum = 0.f;
#pragma unroll
    for (int k = 0; k < 32; k++) sum += ex2f(args[k] - m);
#pragma unroll
    for (int off = 16; off; off >>= 1)
        sum += __shfl_xor_sync(0xffffffffu, sum, off);
    if (lane == 0)
        dout[row] = -10.0f - m - __log2f(sum);   // plain store, fenced in tree_sync
}

__global__ void __launch_bounds__(NTH, 1)
emd_kernel(const float* __restrict__ tgt,    // [1024,3]
           const float* __restrict__ outp,   // [1024,3]
           const int*   __restrict__ iters_ptr,
           float*       __restrict__ out) {
    extern __shared__ __align__(16) float smem[];
    float* sSC  = smem;                // [8][1024]  S*C rows
    float* sSCT = smem + 8 * 1024;     // [8][1024]  S*C^T rows
    __shared__ float red[NTH];

    const int tid  = threadIdx.x;
    const int w    = tid >> 5;
    const int lane = tid & 31;
    const int bid  = (int)blockIdx.x;
    const int gi   = bid >> 3;
    const int row  = (bid << 3) + w;

    // Per-launch monotone-gen base. Safe: d_gen cannot advance before every
    // CTA (including this one) arrives at barrier 1, which is after this read.
    unsigned base = 0;
    if (tid == 0) base = *(volatile unsigned*)&d_gen;

    // ---- Phase A (CTA-local): build SMEM cost slices from point clouds ----
    {
        const float tx = tgt[row * 3 + 0], ty = tgt[row * 3 + 1], tz = tgt[row * 3 + 2];
        for (int j = lane; j < Nn; j += 32) {
            const float dx = tx - outp[j * 3 + 0];
            const float dy = ty - outp[j * 3 + 1];
            const float dz = tz - outp[j * 3 + 2];
            sSC[(w << 10) + j] = S_CONST * (dx * dx + dy * dy + dz * dz);
        }
        const float ox = outp[row * 3 + 0], oy = outp[row * 3 + 1], oz = outp[row * 3 + 2];
        for (int i = lane; i < Nn; i += 32) {
            const float dx = tgt[i * 3 + 0] - ox;
            const float dy = tgt[i * 3 + 1] - oy;
            const float dz = tgt[i * 3 + 2] - oz;
            sSCT[(w << 10) + i] = S_CONST * (dx * dx + dy * dy + dz * dz);
        }
    }
    __syncthreads();

    // ---- Phase B: Sinkhorn iterations ----
    const int iters = iters_ptr ? iters_ptr[0] : 3000;
    unsigned k = 0;   // local barrier count; n_abs = base + k
    {   // iteration 0: g == 0
        half_pass<false>(sSC, (const float*)0, d_Sf, w, lane, row);
        tree_sync(base + (k++), gi);
        half_pass<true>(sSCT, d_Sf, d_Sg, w, lane, row);
        tree_sync(base + (k++), gi);
    }
    for (int it = 1; it < iters; it++) {
        half_pass<true>(sSC,  d_Sg, d_Sf, w, lane, row);
        tree_sync(base + (k++), gi);
        half_pass<true>(sSCT, d_Sf, d_Sg, w, lane, row);
        tree_sync(base + (k++), gi);
    }

    // ---- Phase C: rowsum_i = sum_j exp2(Sf_i + Sg_j - SC_ij) * SC_ij ----
    {
        const float sfr = d_Sf[row];
        const float4* c4 = (const float4*)(sSC + (w << 10));
        const float4* g4 = (const float4*)d_Sg;
        float acc = 0.f;
#pragma unroll
        for (int kk = 0; kk < 8; kk++) {
            const int idx = (kk << 5) + lane;
            const float4 c = c4[idx];
            const float4 g = g4[idx];
            acc += ex2f(sfr + g.x - c.x) * c.x;
            acc += ex2f(sfr + g.y - c.y) * c.y;
            acc += ex2f(sfr + g.z - c.z) * c.z;
            acc += ex2f(sfr + g.w - c.w) * c.w;
        }
#pragma unroll
        for (int off = 16; off; off >>= 1)
            acc += __shfl_xor_sync(0xffffffffu, acc, off);
        if (lane == 0) d_rowsum[row] = acc;
    }
    tree_sync(base + (k++), gi);

    // ---- Deterministic final reduction by CTA 0; scale by 1/S ----
    if (bid == 0) {
        float v = 0.f;
        for (int i = tid; i < Nn; i += NTH) v += d_rowsum[i];
        red[tid] = v;
        __syncthreads();
        for (int s = NTH >> 1; s > 0; s >>= 1) {
            if (tid < s) red[tid] += red[tid + s];
            __syncthreads();
        }
        if (tid == 0) out[0] = red[0] * INV_S;
    }
    // Counters all end at 0 (leaders reset after each use); d_gen is monotone
    // with per-launch base => graph replays are clean without a handshake.
}

extern "C" void kernel_launch(void* const* d_in, const int* in_sizes, int n_in,
                              void* d_out, int out_size) {
    const float* tgt  = (const float*)d_in[0];
    const float* outp = (const float*)d_in[1];
    const int*   itp  = (n_in >= 3) ? (const int*)d_in[2] : nullptr;
    (void)in_sizes; (void)out_size;
    cudaFuncSetAttribute(emd_kernel, cudaFuncAttributeMaxDynamicSharedMemorySize,
                         SMEM_BYTES);
    emd_kernel<<<NCTA, NTH, SMEM_BYTES>>>(tgt, outp, itp, (float*)d_out);
}